// round 6
// baseline (speedup 1.0000x reference)
#include <cuda_runtime.h>
#include <cuda_fp16.h>
#include <math.h>

#define Bb 4
#define Nn 20000
#define Uu 64
#define Ff 65
#define Ee 640000
#define NODES (Bb*Nn)
#define ATT_SCALE 0.125f
#define FP 68          // padded weight row stride (floats)
#define XS 36          // gru: f-major x row stride (32 nodes)
#define XSQ 68         // qkv: f-major x row stride (64 nodes + pad)

typedef unsigned long long ull;

__device__ __forceinline__ ull pack2(float v) {
    ull r; asm("mov.b64 %0, {%1, %1};" : "=l"(r) : "f"(v)); return r;
}
__device__ __forceinline__ void fma2(ull &acc, ull x, ull w) {
    asm("fma.rn.f32x2 %0, %1, %2, %0;" : "+l"(acc) : "l"(x), "l"(w));
}
__device__ __forceinline__ float2 unpack2(ull v) {
    float2 f; asm("mov.b64 {%0, %1}, %2;" : "=f"(f.x), "=f"(f.y) : "l"(v)); return f;
}

// ---------------- device scratch (static, no runtime alloc) ----------------
__device__ __align__(16) __half g_qh[NODES*Uu];   // prescaled by ATT_SCALE
__device__ __align__(16) __half g_kh[NODES*Uu];
__device__ __align__(16) __half g_vh[NODES*Uu];
__device__ __align__(16) float  g_agg[NODES*Uu];
__device__ unsigned char g_mask[NODES];
__device__ int g_cnt[Nn];
__device__ int g_off[Nn];
__device__ int g_cur[Nn];
__device__ int g_srt[Ee];   // src ids sorted by dst (CSR payload)

// ---------------- CSR build ----------------
__global__ void hist_kernel(const int* __restrict__ edst) {
    int i = blockIdx.x * blockDim.x + threadIdx.x;
    if (i < Ee/4) {
        int4 d = ((const int4*)edst)[i];
        atomicAdd(&g_cnt[d.x], 1);
        atomicAdd(&g_cnt[d.y], 1);
        atomicAdd(&g_cnt[d.z], 1);
        atomicAdd(&g_cnt[d.w], 1);
    }
}

__global__ void scan_kernel() {
    __shared__ int sp[1024];
    int tid = threadIdx.x;
    int base = tid * 20;
    int s = 0;
    #pragma unroll
    for (int i = 0; i < 20; i++) {
        int idx = base + i;
        if (idx < Nn) s += g_cnt[idx];
    }
    sp[tid] = s;
    __syncthreads();
    for (int d = 1; d < 1024; d <<= 1) {
        int v = (tid >= d) ? sp[tid - d] : 0;
        __syncthreads();
        sp[tid] += v;
        __syncthreads();
    }
    int run = sp[tid] - s;   // exclusive prefix
    #pragma unroll
    for (int i = 0; i < 20; i++) {
        int idx = base + i;
        if (idx < Nn) {
            g_off[idx] = run;
            g_cur[idx] = run;
            run += g_cnt[idx];
        }
    }
}

__global__ void scatter_kernel(const int* __restrict__ edst,
                               const int* __restrict__ esrc) {
    int i = blockIdx.x * blockDim.x + threadIdx.x;
    if (i < Ee/4) {
        int4 d = ((const int4*)edst)[i];
        int4 s = ((const int4*)esrc)[i];
        int p0 = atomicAdd(&g_cur[d.x], 1); g_srt[p0] = s.x;
        int p1 = atomicAdd(&g_cur[d.y], 1); g_srt[p1] = s.y;
        int p2 = atomicAdd(&g_cur[d.z], 1); g_srt[p2] = s.z;
        int p3 = atomicAdd(&g_cur[d.w], 1); g_srt[p3] = s.w;
    }
}

// ---------------- QKV projection + mask (f32x2, 64-node chunks) -----------
__global__ void __launch_bounds__(256, 2) qkv_kernel(
    const float* __restrict__ inputs, const float* __restrict__ state,
    const float* __restrict__ Wq, const float* __restrict__ bq,
    const float* __restrict__ Wk, const float* __restrict__ bk,
    const float* __restrict__ Wv, const float* __restrict__ bv)
{
    extern __shared__ float sm[];
    float* sWqT = sm;                  // 64*FP   (W[u][f], zero-padded f=65..67)
    float* sWkT = sWqT + 64*FP;
    float* sWvT = sWkT + 64*FP;
    float* sb   = sWvT + 64*FP;        // 192
    float* sxT  = sb + 192;            // 68*XSQ  (x[f][node], 64 nodes)

    for (int i = threadIdx.x; i < Ff*Uu; i += 256) {
        int f = i >> 6, u = i & 63;
        sWqT[u*FP + f] = Wq[i];
        sWkT[u*FP + f] = Wk[i];
        sWvT[u*FP + f] = Wv[i];
    }
    for (int i = threadIdx.x; i < 192; i += 256) {
        int u = i & 63, p = i >> 6;    // pad f=65..67
        sWqT[u*FP + 65 + p] = 0.f;
        sWkT[u*FP + 65 + p] = 0.f;
        sWvT[u*FP + 65 + p] = 0.f;
    }
    if (threadIdx.x < 192) sb[threadIdx.x] =
        (threadIdx.x < 64) ? bq[threadIdx.x] :
        (threadIdx.x < 128) ? bk[threadIdx.x - 64] : bv[threadIdx.x - 128];
    if (threadIdx.x < 192) {           // zero pad rows 65..67 (64 nodes)
        int r = 65 + threadIdx.x / 64;
        sxT[r*XSQ + (threadIdx.x & 63)] = 0.f;
    }
    __syncthreads();

    int u = threadIdx.x & 63;
    int g = threadIdx.x >> 6;
    int ln0 = g * 16;
    const float4* wq4 = (const float4*)(sWqT + u*FP);
    const float4* wk4 = (const float4*)(sWkT + u*FP);
    const float4* wv4 = (const float4*)(sWvT + u*FP);

    for (int c = blockIdx.x; c < NODES/64; c += gridDim.x) {
        int base = c * 64;
        __syncthreads();
        // stage f-major: coalesced float4 reads, scalar transposed writes
        #pragma unroll
        for (int i = threadIdx.x; i < 1024; i += 256) {
            int node = i >> 4, f4 = i & 15;
            float4 v = ((const float4*)state)[(size_t)(base + node)*16 + f4];
            sxT[(f4*4+0)*XSQ + node] = v.x;
            sxT[(f4*4+1)*XSQ + node] = v.y;
            sxT[(f4*4+2)*XSQ + node] = v.z;
            sxT[(f4*4+3)*XSQ + node] = v.w;
        }
        if (threadIdx.x < 64) {
            int node = base + threadIdx.x;
            sxT[64*XSQ + threadIdx.x] = inputs[node];
            g_mask[node] = (__ldg(&state[(size_t)node*Uu + 58]) != 0.f) ? 1 : 0;
        }
        __syncthreads();

        ull aq[8], ak[8], av[8];
        #pragma unroll
        for (int p = 0; p < 8; p++) { aq[p]=0ull; ak[p]=0ull; av[p]=0ull; }

        #pragma unroll 4
        for (int f4 = 0; f4 < 17; f4++) {
            float4 wq = wq4[f4], wk = wk4[f4], wv = wv4[f4];
            #pragma unroll
            for (int e = 0; e < 4; e++) {
                int f = f4*4 + e;
                ulonglong2 x01 = *(const ulonglong2*)(sxT + f*XSQ + ln0);
                ulonglong2 x23 = *(const ulonglong2*)(sxT + f*XSQ + ln0 + 4);
                ulonglong2 x45 = *(const ulonglong2*)(sxT + f*XSQ + ln0 + 8);
                ulonglong2 x67 = *(const ulonglong2*)(sxT + f*XSQ + ln0 + 12);
                float wqe = (e==0)?wq.x:(e==1)?wq.y:(e==2)?wq.z:wq.w;
                float wke = (e==0)?wk.x:(e==1)?wk.y:(e==2)?wk.z:wk.w;
                float wve = (e==0)?wv.x:(e==1)?wv.y:(e==2)?wv.z:wv.w;
                ull wq2 = pack2(wqe), wk2 = pack2(wke), wv2 = pack2(wve);
                fma2(aq[0], x01.x, wq2); fma2(aq[1], x01.y, wq2);
                fma2(aq[2], x23.x, wq2); fma2(aq[3], x23.y, wq2);
                fma2(aq[4], x45.x, wq2); fma2(aq[5], x45.y, wq2);
                fma2(aq[6], x67.x, wq2); fma2(aq[7], x67.y, wq2);
                fma2(ak[0], x01.x, wk2); fma2(ak[1], x01.y, wk2);
                fma2(ak[2], x23.x, wk2); fma2(ak[3], x23.y, wk2);
                fma2(ak[4], x45.x, wk2); fma2(ak[5], x45.y, wk2);
                fma2(ak[6], x67.x, wk2); fma2(ak[7], x67.y, wk2);
                fma2(av[0], x01.x, wv2); fma2(av[1], x01.y, wv2);
                fma2(av[2], x23.x, wv2); fma2(av[3], x23.y, wv2);
                fma2(av[4], x45.x, wv2); fma2(av[5], x45.y, wv2);
                fma2(av[6], x67.x, wv2); fma2(av[7], x67.y, wv2);
            }
        }
        float bqv = sb[u], bkv = sb[64+u], bvv = sb[128+u];
        #pragma unroll
        for (int p = 0; p < 8; p++) {
            float2 fq = unpack2(aq[p]);
            float2 fk = unpack2(ak[p]);
            float2 fv = unpack2(av[p]);
            size_t i0 = (size_t)(base + ln0 + 2*p)*Uu + u;
            g_qh[i0]      = __float2half_rn((fq.x + bqv) * ATT_SCALE);
            g_qh[i0 + Uu] = __float2half_rn((fq.y + bqv) * ATT_SCALE);
            g_kh[i0]      = __float2half_rn(fk.x + bkv);
            g_kh[i0 + Uu] = __float2half_rn(fk.y + bkv);
            g_vh[i0]      = __float2half_rn(fv.x + bvv);
            g_vh[i0 + Uu] = __float2half_rn(fv.y + bvv);
        }
    }
}

// ---------------- attention: one warp per (b, dst), 8 lanes per edge -------
// 16 edges in flight per iteration (4 slots per group) for deep MLP.
__device__ __forceinline__ void ld_h8(const __half* p, float2 f[4]) {
    uint4 r = *reinterpret_cast<const uint4*>(p);
    f[0] = __half22float2(*reinterpret_cast<__half2*>(&r.x));
    f[1] = __half22float2(*reinterpret_cast<__half2*>(&r.y));
    f[2] = __half22float2(*reinterpret_cast<__half2*>(&r.z));
    f[3] = __half22float2(*reinterpret_cast<__half2*>(&r.w));
}

__global__ void __launch_bounds__(256) attn_kernel() {
    int gw = (blockIdx.x * blockDim.x + threadIdx.x) >> 5;
    if (gw >= NODES) return;
    if (!g_mask[gw]) return;

    int lane = threadIdx.x & 31;
    int grp  = lane >> 3;     // edge slot group 0..3
    int sub  = lane & 7;      // dim group: dims [sub*8, sub*8+8)
    int b = gw / Nn;
    int n = gw - b * Nn;

    size_t rowbase = (size_t)gw * Uu;
    float2 q[4];
    ld_h8(g_qh + rowbase + sub*8, q);

    int off = g_off[n];
    int deg = g_cnt[n];
    int end = off + deg;
    const __half* kb = g_kh + (size_t)b * Nn * Uu;
    const __half* vb = g_vh + (size_t)b * Nn * Uu;
    const unsigned char* mk = g_mask + b * Nn;

    float2 acc[4] = {{0,0},{0,0},{0,0},{0,0}};
    float den = 0.f;

    int s[4]; bool vl[4];
    #pragma unroll
    for (int j = 0; j < 4; j++) {
        int e = off + 4*j + grp;
        vl[j] = e < end;
        s[j] = 0;
    }
    if (off < end) {
        #pragma unroll
        for (int j = 0; j < 4; j++)
            s[j] = __ldg(&g_srt[vl[j] ? (off + 4*j + grp) : off]);
    }

    for (int t = off; t < end; t += 16) {
        int cs[4]; bool cv[4];
        #pragma unroll
        for (int j = 0; j < 4; j++) { cs[j] = s[j]; cv[j] = vl[j]; }
        int tn = t + 16;
        if (tn < end) {        // prefetch next block's src ids
            #pragma unroll
            for (int j = 0; j < 4; j++) {
                int e = tn + 4*j + grp;
                vl[j] = e < end;
                s[j] = __ldg(&g_srt[vl[j] ? e : off]);
            }
        }

        // issue all loads up-front (mask, k, v for 4 edges)
        unsigned m[4];
        float2 kk[4][4], vv[4][4];
        #pragma unroll
        for (int j = 0; j < 4; j++) m[j] = mk[cs[j]];
        #pragma unroll
        for (int j = 0; j < 4; j++) {
            ld_h8(kb + (size_t)cs[j] * Uu + sub*8, kk[j]);
            ld_h8(vb + (size_t)cs[j] * Uu + sub*8, vv[j]);
        }

        float p[4];
        #pragma unroll
        for (int j = 0; j < 4; j++) {
            p[j] = kk[j][0].x*q[0].x + kk[j][0].y*q[0].y
                 + kk[j][1].x*q[1].x + kk[j][1].y*q[1].y
                 + kk[j][2].x*q[2].x + kk[j][2].y*q[2].y
                 + kk[j][3].x*q[3].x + kk[j][3].y*q[3].y;
        }
        #pragma unroll
        for (int d = 1; d < 8; d <<= 1) {
            #pragma unroll
            for (int j = 0; j < 4; j++)
                p[j] += __shfl_xor_sync(0xffffffffu, p[j], d);
        }
        float w[4];
        #pragma unroll
        for (int j = 0; j < 4; j++)
            w[j] = (cv[j] && m[j]) ? __expf(p[j]) : 0.f;

        #pragma unroll
        for (int j = 0; j < 4; j++) {
            #pragma unroll
            for (int i = 0; i < 4; i++) {
                acc[i].x += w[j] * vv[j][i].x;
                acc[i].y += w[j] * vv[j][i].y;
            }
            den += w[j];
        }
    }

    // cross-group reduce (groups 0..3 hold disjoint edge subsets)
    #pragma unroll
    for (int d = 8; d < 32; d <<= 1) {
        #pragma unroll
        for (int i = 0; i < 4; i++) {
            acc[i].x += __shfl_xor_sync(0xffffffffu, acc[i].x, d);
            acc[i].y += __shfl_xor_sync(0xffffffffu, acc[i].y, d);
        }
        den += __shfl_xor_sync(0xffffffffu, den, d);
    }

    if (lane < 8) {
        float inv = (den > 0.f) ? 1.f / fmaxf(den, 1e-16f) : 0.f;
        float4* op = (float4*)(g_agg + rowbase + sub * 8);
        op[0] = make_float4(acc[0].x*inv, acc[0].y*inv, acc[1].x*inv, acc[1].y*inv);
        op[1] = make_float4(acc[2].x*inv, acc[2].y*inv, acc[3].x*inv, acc[3].y*inv);
    }
}

// ---------------- fused GRU epilogue (f32x2 packed FMA) ----------------
__global__ void __launch_bounds__(256) gru_kernel(
    const float* __restrict__ inputs, const float* __restrict__ state,
    const float* __restrict__ Ws, const float* __restrict__ bs,
    const float* __restrict__ W1, const float* __restrict__ b1,
    const float* __restrict__ W2, const float* __restrict__ b2,
    float* __restrict__ out)
{
    extern __shared__ float sm[];
    float* sWsT  = sm;                   // 64*FP
    float* sW1aT = sWsT  + 64*FP;        // cols 0..63
    float* sW1bT = sW1aT + 64*FP;        // cols 64..127
    float* sW2T  = sW1bT + 64*FP;
    float* sbs = sW2T + 64*FP;           // 64
    float* sb1 = sbs + 64;               // 128
    float* sb2 = sb1 + 128;              // 64
    float* sxT   = sb2 + 64;             // 68*XS  x = [h, xin] f-major
    float* sh2T  = sxT  + 68*XS;         // 68*XS  cat1 = [xin, h2]
    float* srh2T = sh2T + 68*XS;         // 68*XS  [xin, reset*h2]

    for (int i = threadIdx.x; i < Ff*Uu; i += 256) {
        int f = i >> 6, u = i & 63;
        sWsT[u*FP + f] = Ws[i];
        sW2T[u*FP + f] = W2[i];
    }
    for (int i = threadIdx.x; i < Ff*128; i += 256) {
        int f = i >> 7, c = i & 127;
        if (c < 64) sW1aT[c*FP + f] = W1[i];
        else        sW1bT[(c-64)*FP + f] = W1[i];
    }
    for (int i = threadIdx.x; i < 192; i += 256) {
        int u = i & 63, p = i >> 6;
        sWsT[u*FP + 65 + p] = 0.f;
        sW1aT[u*FP + 65 + p] = 0.f;
        sW1bT[u*FP + 65 + p] = 0.f;
        sW2T[u*FP + 65 + p] = 0.f;
    }
    if (threadIdx.x < 64)  sbs[threadIdx.x] = bs[threadIdx.x];
    if (threadIdx.x < 128) sb1[threadIdx.x] = b1[threadIdx.x];
    if (threadIdx.x < 64)  sb2[threadIdx.x] = b2[threadIdx.x];
    if (threadIdx.x < 96) {              // zero pad rows 65..67 once
        int r = 65 + threadIdx.x / 32;
        int nl = threadIdx.x & 31;
        sxT[r*XS + nl] = 0.f;
        sh2T[r*XS + nl] = 0.f;
        srh2T[r*XS + nl] = 0.f;
    }
    __syncthreads();

    int u = threadIdx.x & 63;
    int g = threadIdx.x >> 6;
    int ln0 = g * 8;
    const float4* ws4  = (const float4*)(sWsT  + u*FP);
    const float4* w1a4 = (const float4*)(sW1aT + u*FP);
    const float4* w1b4 = (const float4*)(sW1bT + u*FP);
    const float4* w24  = (const float4*)(sW2T  + u*FP);

    for (int c = blockIdx.x; c < NODES/32; c += gridDim.x) {
        int base = c * 32;
        __syncthreads();
        #pragma unroll
        for (int i = threadIdx.x; i < 512; i += 256) {
            int node = i >> 4, f4 = i & 15;
            float4 v = ((const float4*)state)[(size_t)(base + node)*16 + f4];
            sxT[(f4*4+0)*XS + node] = v.x;
            sxT[(f4*4+1)*XS + node] = v.y;
            sxT[(f4*4+2)*XS + node] = v.z;
            sxT[(f4*4+3)*XS + node] = v.w;
        }
        if (threadIdx.x < 32) {
            sxT[64*XS + threadIdx.x] = inputs[base + threadIdx.x];
        }
        __syncthreads();

        // phase 1: s = x @ Ws
        ull acc[4];
        #pragma unroll
        for (int p = 0; p < 4; p++) acc[p] = 0ull;
        #pragma unroll 4
        for (int f4 = 0; f4 < 17; f4++) {
            float4 w = ws4[f4];
            #pragma unroll
            for (int e = 0; e < 4; e++) {
                int f = f4*4 + e;
                ulonglong2 xab = *(const ulonglong2*)(sxT + f*XS + ln0);
                ulonglong2 xcd = *(const ulonglong2*)(sxT + f*XS + ln0 + 4);
                float we = (e==0)?w.x:(e==1)?w.y:(e==2)?w.z:w.w;
                ull w2 = pack2(we);
                fma2(acc[0], xab.x, w2); fma2(acc[1], xab.y, w2);
                fma2(acc[2], xcd.x, w2); fma2(acc[3], xcd.y, w2);
            }
        }
        float sres[8];
        #pragma unroll
        for (int p = 0; p < 4; p++) {
            float2 f2 = unpack2(acc[p]);
            sres[2*p] = f2.x; sres[2*p+1] = f2.y;
        }

        float h2v[8], xinv[8];
        float bsu = sbs[u];
        #pragma unroll
        for (int j = 0; j < 8; j++) {
            int nl = ln0 + j;
            int node = base + nl;
            float hv  = sxT[u*XS + nl];
            xinv[j]   = sxT[64*XS + nl];
            bool msk  = (sxT[58*XS + nl] != 0.f);
            float av  = g_agg[(size_t)node*Uu + u];
            float h2  = msk ? (av + sres[j] + bsu) : hv;
            h2v[j] = h2;
            sh2T[(1+u)*XS + nl] = h2;
            if (u == 0) sh2T[nl] = xinv[j];
        }
        __syncthreads();

        // phase 2: value = sigmoid(cat1 @ W1 + b1)
        ull a1[4], a2[4];
        ull b1a = pack2(sb1[u]), b1b = pack2(sb1[64+u]);
        #pragma unroll
        for (int p = 0; p < 4; p++) { a1[p] = b1a; a2[p] = b1b; }
        #pragma unroll 4
        for (int f4 = 0; f4 < 17; f4++) {
            float4 wa = w1a4[f4], wb = w1b4[f4];
            #pragma unroll
            for (int e = 0; e < 4; e++) {
                int f = f4*4 + e;
                ulonglong2 xab = *(const ulonglong2*)(sh2T + f*XS + ln0);
                ulonglong2 xcd = *(const ulonglong2*)(sh2T + f*XS + ln0 + 4);
                float wae = (e==0)?wa.x:(e==1)?wa.y:(e==2)?wa.z:wa.w;
                float wbe = (e==0)?wb.x:(e==1)?wb.y:(e==2)?wb.z:wb.w;
                ull wa2 = pack2(wae), wb2 = pack2(wbe);
                fma2(a1[0], xab.x, wa2); fma2(a1[1], xab.y, wa2);
                fma2(a1[2], xcd.x, wa2); fma2(a1[3], xcd.y, wa2);
                fma2(a2[0], xab.x, wb2); fma2(a2[1], xab.y, wb2);
                fma2(a2[2], xcd.x, wb2); fma2(a2[3], xcd.y, wb2);
            }
        }
        float zz[8];
        #pragma unroll
        for (int p = 0; p < 4; p++) {
            float2 f1 = unpack2(a1[p]);
            float2 f2 = unpack2(a2[p]);
            float rst0 = 1.f / (1.f + __expf(-f1.x));
            float rst1 = 1.f / (1.f + __expf(-f1.y));
            zz[2*p]   = 1.f / (1.f + __expf(-f2.x));
            zz[2*p+1] = 1.f / (1.f + __expf(-f2.y));
            int nl0 = ln0 + 2*p;
            srh2T[(1+u)*XS + nl0]     = rst0 * h2v[2*p];
            srh2T[(1+u)*XS + nl0 + 1] = rst1 * h2v[2*p+1];
            if (u == 0) {
                srh2T[nl0] = xinv[2*p];
                srh2T[nl0 + 1] = xinv[2*p+1];
            }
        }
        __syncthreads();

        // phase 3: c = tanh([xin, reset*h2] @ W2 + b2)
        ull cacc[4];
        ull b2p = pack2(sb2[u]);
        #pragma unroll
        for (int p = 0; p < 4; p++) cacc[p] = b2p;
        #pragma unroll 4
        for (int f4 = 0; f4 < 17; f4++) {
            float4 w = w24[f4];
            #pragma unroll
            for (int e = 0; e < 4; e++) {
                int f = f4*4 + e;
                ulonglong2 xab = *(const ulonglong2*)(srh2T + f*XS + ln0);
                ulonglong2 xcd = *(const ulonglong2*)(srh2T + f*XS + ln0 + 4);
                float we = (e==0)?w.x:(e==1)?w.y:(e==2)?w.z:w.w;
                ull w2 = pack2(we);
                fma2(cacc[0], xab.x, w2); fma2(cacc[1], xab.y, w2);
                fma2(cacc[2], xcd.x, w2); fma2(cacc[3], xcd.y, w2);
            }
        }
        #pragma unroll
        for (int p = 0; p < 4; p++) {
            float2 f2 = unpack2(cacc[p]);
            int j0 = 2*p;
            float cc0 = tanhf(f2.x), cc1 = tanhf(f2.y);
            size_t i0 = (size_t)(base + ln0 + j0)*Uu + u;
            out[i0]      = (1.f - zz[j0])   * h2v[j0]   + zz[j0]   * cc0;
            out[i0 + Uu] = (1.f - zz[j0+1]) * h2v[j0+1] + zz[j0+1] * cc1;
        }
    }
}

// ---------------- launch ----------------
extern "C" void kernel_launch(void* const* d_in, const int* in_sizes, int n_in,
                              void* d_out, int out_size)
{
    const float* inputs = (const float*)d_in[0];
    const float* state  = (const float*)d_in[1];
    const int*   esrc   = (const int*)d_in[2];
    const int*   edst   = (const int*)d_in[3];
    const float* Wq = (const float*)d_in[4];
    const float* bq = (const float*)d_in[5];
    const float* Wk = (const float*)d_in[6];
    const float* bk = (const float*)d_in[7];
    const float* Wv = (const float*)d_in[8];
    const float* bv = (const float*)d_in[9];
    const float* Ws = (const float*)d_in[10];
    const float* bs = (const float*)d_in[11];
    const float* W1 = (const float*)d_in[12];
    const float* b1 = (const float*)d_in[13];
    const float* W2 = (const float*)d_in[14];
    const float* b2 = (const float*)d_in[15];
    float* out = (float*)d_out;

    const int SMEM_A = (3*64*FP + 192 + 68*XSQ) * (int)sizeof(float);
    const int SMEM_D = (4*64*FP + 256 + 3*68*XS) * (int)sizeof(float);

    cudaFuncSetAttribute(qkv_kernel, cudaFuncAttributeMaxDynamicSharedMemorySize, SMEM_A);
    cudaFuncSetAttribute(gru_kernel, cudaFuncAttributeMaxDynamicSharedMemorySize, SMEM_D);

    // CSR build (counts zeroed by async memset; graph-capturable, no alloc)
    void* cnt_ptr = nullptr;
    cudaGetSymbolAddress(&cnt_ptr, g_cnt);
    cudaMemsetAsync(cnt_ptr, 0, Nn * sizeof(int), 0);
    hist_kernel<<<(Ee/4 + 255)/256, 256>>>(edst);
    scan_kernel<<<1, 1024>>>();
    scatter_kernel<<<(Ee/4 + 255)/256, 256>>>(edst, esrc);

    // projections (64-node chunks, 2 CTAs/SM)
    qkv_kernel<<<296, 256, SMEM_A>>>(inputs, state, Wq, bq, Wk, bk, Wv, bv);

    // attention: one warp per (b, dst), 16 edges in flight
    attn_kernel<<<(NODES*32 + 255)/256, 256>>>();

    // fused GRU
    gru_kernel<<<296, 256, SMEM_D>>>(inputs, state, Ws, bs, W1, b1, W2, b2, out);
}